// round 10
// baseline (speedup 1.0000x reference)
#include <cuda_runtime.h>
#include <cuda_fp16.h>
#include <math.h>

#define N_NODES 150000
#define N_EDGES 2400000
#define F_IN 128
#define HID 32
#define SCAN_BS 256
#define SCAN_NB ((N_NODES + SCAN_BS - 1) / SCAN_BS)   // 586

#define EDGE_BLKS 2344        // 600000 edge-quads / 256 (rounded up)
#define X1_BLKS 2344          // ceil(150000/64) rows, 64 rows/block
#define HIST_BLKS 1172        // 8 edges/thread

// Scratch (allocation-free rule: __device__ globals)
__device__ float  g_dinv[N_NODES];
__device__ __half g_tmp[(size_t)N_NODES * HID];    // fp16 messages (9.6 MB)
__device__ __half g_acc[(size_t)N_NODES * HID];
__device__ float  g_tmp3[N_NODES];
__device__ int    g_cnt[N_NODES];
__device__ int    g_rowptr[N_NODES + 1];
__device__ int    g_cursor[N_NODES];
__device__ int    g_bsum[1024];
__device__ int    g_csr_src[N_EDGES];

// ---------------- hist: 8 edges per thread ----------------
__global__ __launch_bounds__(256) void k_hist(const int* __restrict__ dst) {
    int t = blockIdx.x * blockDim.x + threadIdx.x;
    int q0 = t * 2;
    if (q0 < N_EDGES / 4) {
        int4 d = __ldg((const int4*)dst + q0);
        atomicAdd(&g_cnt[d.x], 1);
        atomicAdd(&g_cnt[d.y], 1);
        atomicAdd(&g_cnt[d.z], 1);
        atomicAdd(&g_cnt[d.w], 1);
    }
    if (q0 + 1 < N_EDGES / 4) {
        int4 d = __ldg((const int4*)dst + q0 + 1);
        atomicAdd(&g_cnt[d.x], 1);
        atomicAdd(&g_cnt[d.y], 1);
        atomicAdd(&g_cnt[d.z], 1);
        atomicAdd(&g_cnt[d.w], 1);
    }
}

// ---------------- scan A ----------------
__global__ void k_scan_a() {
    __shared__ int wsum[8];
    int tid = threadIdx.x;
    int lane = tid & 31, w = tid >> 5;
    int i = blockIdx.x * SCAN_BS + tid;
    int v = (i < N_NODES) ? g_cnt[i] : 0;
    int s = v;
#pragma unroll
    for (int o = 1; o < 32; o <<= 1) {
        int t = __shfl_up_sync(0xffffffffu, s, o);
        if (lane >= o) s += t;
    }
    if (lane == 31) wsum[w] = s;
    __syncthreads();
    if (w == 0 && lane < 8) {
        int ws = wsum[lane];
#pragma unroll
        for (int o = 1; o < 8; o <<= 1) {
            int t = __shfl_up_sync(0xffu, ws, o);
            if (lane >= o) ws += t;
        }
        wsum[lane] = ws;
    }
    __syncthreads();
    int incl = s + (w > 0 ? wsum[w - 1] : 0);
    if (i < N_NODES) g_rowptr[i] = incl - v;
    if (tid == SCAN_BS - 1) g_bsum[blockIdx.x] = incl;
}

// ---------------- scan C (fused B): each block sums bsum[0..blk) itself ----------------
__global__ void k_scan_c() {
    __shared__ int red[8];
    __shared__ int s_off;
    int tid = threadIdx.x;
    int lane = tid & 31, w = tid >> 5;
    int blk = blockIdx.x;
    int p = 0;
    for (int j = tid; j < blk; j += 256) p += g_bsum[j];
#pragma unroll
    for (int o = 16; o > 0; o >>= 1) p += __shfl_down_sync(0xffffffffu, p, o);
    if (lane == 0) red[w] = p;
    __syncthreads();
    if (tid == 0) {
        int t = 0;
#pragma unroll
        for (int k = 0; k < 8; k++) t += red[k];
        s_off = t;
    }
    __syncthreads();
    int off = s_off;
    int i = blk * 256 + tid;
    if (i < N_NODES) {
        int r = g_rowptr[i] + off;
        g_rowptr[i] = r;
        g_cursor[i] = r;
        g_dinv[i] = rsqrtf((float)(g_cnt[i] + 1));  // +1 self loop
    }
    if (i == 0) g_rowptr[N_NODES] = N_EDGES;
}

// ---------------- F2: interleaved fill (even) + xform1 direct-gmem (odd) ----------------
// xform: warp handles 8 rows; all lanes broadcast-read the same x float4 (L1-resident),
// lane = output feature. Only sW (16 KB) in shared -> 8 blocks/SM.
__global__ __launch_bounds__(256) void k_F2(const int* __restrict__ src,
                                            const int* __restrict__ dst,
                                            const float* __restrict__ x,
                                            const float* __restrict__ W1) {
    __shared__ __align__(16) float sW[F_IN * HID];   // 16 KB
    int tid = threadIdx.x;
    int half_idx = blockIdx.x >> 1;
    if ((blockIdx.x & 1) == 0) {
        int t = half_idx * 256 + tid;
        if (t < N_EDGES / 4) {
            int4 s = __ldg((const int4*)src + t);
            int4 d = __ldg((const int4*)dst + t);
            g_csr_src[atomicAdd(&g_cursor[d.x], 1)] = s.x;
            g_csr_src[atomicAdd(&g_cursor[d.y], 1)] = s.y;
            g_csr_src[atomicAdd(&g_cursor[d.z], 1)] = s.z;
            g_csr_src[atomicAdd(&g_cursor[d.w], 1)] = s.w;
        }
    } else {
        {
            const float4* Wv = (const float4*)W1;
            float4* sWv = (float4*)sW;
#pragma unroll
            for (int i = 0; i < 4; i++) sWv[tid + i * 256] = Wv[tid + i * 256];
        }
        __syncthreads();
        int w = tid >> 5, f = tid & 31;
        int row0 = half_idx * 64 + w * 8;
        // clamp load base so OOB rows read valid memory (stores are guarded)
        int rl = (row0 + 8 <= N_NODES) ? row0 : (N_NODES - 8);
        const float* xr = x + (size_t)rl * F_IN;
        float acc[8] = {0, 0, 0, 0, 0, 0, 0, 0};
#pragma unroll
        for (int k4 = 0; k4 < F_IN; k4 += 4) {
            float w0 = sW[(k4 + 0) * HID + f];
            float w1 = sW[(k4 + 1) * HID + f];
            float w2 = sW[(k4 + 2) * HID + f];
            float w3 = sW[(k4 + 3) * HID + f];
#pragma unroll
            for (int r = 0; r < 8; r++) {
                float4 xa = __ldg((const float4*)(xr + r * F_IN + k4));
                acc[r] = fmaf(xa.x, w0, fmaf(xa.y, w1, fmaf(xa.z, w2, fmaf(xa.w, w3, acc[r]))));
            }
        }
#pragma unroll
        for (int r = 0; r < 8; r++) {
            int row = rl + r;
            if (row0 + r < N_NODES)   // rl==row0 except tail, where rl covers valid rows
                g_tmp[(size_t)row * HID + f] = __float2half_rn(g_dinv[row] * acc[r]);
        }
    }
}

// ---------------- fused: agg(L1) + relu + @W2 + scale -> g_acc (fp16) ----------------
// 4 edges per lane-group: lane = eidx*8 + fg; 8-edge unrolled main loop for MLP.
__global__ void k_agg_xf2(const float* __restrict__ W2, const float* __restrict__ b1) {
    __shared__ float sW[HID * HID];
    __shared__ float sy[8][HID];
    int tid = threadIdx.x;  // 256
    for (int i = tid; i < HID * HID; i += 256) sW[i] = W2[i];
    __syncthreads();
    int w = tid >> 5, lane = tid & 31;
    int n = blockIdx.x * 8 + w;
    if (n >= N_NODES) return;  // warp-uniform
    int eidx = lane >> 3, fg = lane & 7;
    int e = g_rowptr[n];
    int e1 = g_rowptr[n + 1];
    float ax = 0.f, ay = 0.f, az = 0.f, aw = 0.f;
    for (; e + 8 <= e1; e += 8) {
        int s0 = g_csr_src[e + eidx];
        int s1 = g_csr_src[e + 4 + eidx];
        int2 v0 = *(const int2*)(g_tmp + (size_t)s0 * HID + fg * 4);
        int2 v1 = *(const int2*)(g_tmp + (size_t)s1 * HID + fg * 4);
        float2 a0 = __half22float2(*(__half2*)&v0.x);
        float2 b0 = __half22float2(*(__half2*)&v0.y);
        float2 a1 = __half22float2(*(__half2*)&v1.x);
        float2 b1f = __half22float2(*(__half2*)&v1.y);
        ax += a0.x + a1.x; ay += a0.y + a1.y;
        az += b0.x + b1f.x; aw += b0.y + b1f.y;
    }
    if (e + 4 <= e1) {
        int s = g_csr_src[e + eidx];
        int2 v = *(const int2*)(g_tmp + (size_t)s * HID + fg * 4);
        float2 f0 = __half22float2(*(__half2*)&v.x);
        float2 f1 = __half22float2(*(__half2*)&v.y);
        ax += f0.x; ay += f0.y; az += f1.x; aw += f1.y;
        e += 4;
    }
    if (eidx < e1 - e) {
        int s = g_csr_src[e + eidx];
        int2 v = *(const int2*)(g_tmp + (size_t)s * HID + fg * 4);
        float2 f0 = __half22float2(*(__half2*)&v.x);
        float2 f1 = __half22float2(*(__half2*)&v.y);
        ax += f0.x; ay += f0.y; az += f1.x; aw += f1.y;
    }
#pragma unroll
    for (int o = 8; o <= 16; o <<= 1) {
        ax += __shfl_xor_sync(0xffffffffu, ax, o);
        ay += __shfl_xor_sync(0xffffffffu, ay, o);
        az += __shfl_xor_sync(0xffffffffu, az, o);
        aw += __shfl_xor_sync(0xffffffffu, aw, o);
    }
    // self loop
    {
        int2 v = *(const int2*)(g_tmp + (size_t)n * HID + fg * 4);
        float2 f0 = __half22float2(*(__half2*)&v.x);
        float2 f1 = __half22float2(*(__half2*)&v.y);
        ax += f0.x; ay += f0.y; az += f1.x; aw += f1.y;
    }
    float di = g_dinv[n];
    float4 bv = *(const float4*)(b1 + fg * 4);
    float4 y;
    y.x = fmaxf(fmaf(di, ax, bv.x), 0.0f);
    y.y = fmaxf(fmaf(di, ay, bv.y), 0.0f);
    y.z = fmaxf(fmaf(di, az, bv.z), 0.0f);
    y.w = fmaxf(fmaf(di, aw, bv.w), 0.0f);
    if (eidx == 0) *(float4*)&sy[w][fg * 4] = y;
    __syncwarp();
    float t = 0.0f;
#pragma unroll
    for (int k = 0; k < HID; k++) t = fmaf(sy[w][k], sW[k * HID + lane], t);
    g_acc[(size_t)n * HID + lane] = __float2half_rn(di * t);
}

// ---------------- fused: agg(L2) + relu + dot W3 + scale -> g_tmp3 ----------------
__global__ void k_agg_xf3(const float* __restrict__ W3, const float* __restrict__ b2) {
    int tid = threadIdx.x;
    int w = tid >> 5, lane = tid & 31;
    int n = blockIdx.x * 8 + w;
    if (n >= N_NODES) return;  // warp-uniform
    int eidx = lane >> 3, fg = lane & 7;
    int e = g_rowptr[n];
    int e1 = g_rowptr[n + 1];
    float ax = 0.f, ay = 0.f, az = 0.f, aw = 0.f;
    for (; e + 8 <= e1; e += 8) {
        int s0 = g_csr_src[e + eidx];
        int s1 = g_csr_src[e + 4 + eidx];
        int2 v0 = *(const int2*)(g_acc + (size_t)s0 * HID + fg * 4);
        int2 v1 = *(const int2*)(g_acc + (size_t)s1 * HID + fg * 4);
        float2 a0 = __half22float2(*(__half2*)&v0.x);
        float2 b0 = __half22float2(*(__half2*)&v0.y);
        float2 a1 = __half22float2(*(__half2*)&v1.x);
        float2 b1f = __half22float2(*(__half2*)&v1.y);
        ax += a0.x + a1.x; ay += a0.y + a1.y;
        az += b0.x + b1f.x; aw += b0.y + b1f.y;
    }
    if (e + 4 <= e1) {
        int s = g_csr_src[e + eidx];
        int2 v = *(const int2*)(g_acc + (size_t)s * HID + fg * 4);
        float2 f0 = __half22float2(*(__half2*)&v.x);
        float2 f1 = __half22float2(*(__half2*)&v.y);
        ax += f0.x; ay += f0.y; az += f1.x; aw += f1.y;
        e += 4;
    }
    if (eidx < e1 - e) {
        int s = g_csr_src[e + eidx];
        int2 v = *(const int2*)(g_acc + (size_t)s * HID + fg * 4);
        float2 f0 = __half22float2(*(__half2*)&v.x);
        float2 f1 = __half22float2(*(__half2*)&v.y);
        ax += f0.x; ay += f0.y; az += f1.x; aw += f1.y;
    }
#pragma unroll
    for (int o = 8; o <= 16; o <<= 1) {
        ax += __shfl_xor_sync(0xffffffffu, ax, o);
        ay += __shfl_xor_sync(0xffffffffu, ay, o);
        az += __shfl_xor_sync(0xffffffffu, az, o);
        aw += __shfl_xor_sync(0xffffffffu, aw, o);
    }
    {
        int2 v = *(const int2*)(g_acc + (size_t)n * HID + fg * 4);
        float2 f0 = __half22float2(*(__half2*)&v.x);
        float2 f1 = __half22float2(*(__half2*)&v.y);
        ax += f0.x; ay += f0.y; az += f1.x; aw += f1.y;
    }
    float di = g_dinv[n];
    float4 bv = *(const float4*)(b2 + fg * 4);
    float4 wv = *(const float4*)(W3 + fg * 4);
    float t = fmaxf(fmaf(di, ax, bv.x), 0.0f) * wv.x
            + fmaxf(fmaf(di, ay, bv.y), 0.0f) * wv.y
            + fmaxf(fmaf(di, az, bv.z), 0.0f) * wv.z
            + fmaxf(fmaf(di, aw, bv.w), 0.0f) * wv.w;
#pragma unroll
    for (int o = 1; o <= 4; o <<= 1) t += __shfl_xor_sync(0xffffffffu, t, o);
    if (lane == 0) g_tmp3[n] = di * t;
}

// ---------------- scalar gather + final sigmoid ----------------
__global__ void k_agg1_final(const float* __restrict__ b3, float* __restrict__ out) {
    int n = blockIdx.x * blockDim.x + threadIdx.x;
    if (n >= N_NODES) return;
    int e = g_rowptr[n];
    int e1 = g_rowptr[n + 1];
    float a = g_tmp3[n];  // self loop
    for (; e + 4 <= e1; e += 4) {
        float v0 = g_tmp3[g_csr_src[e + 0]];
        float v1 = g_tmp3[g_csr_src[e + 1]];
        float v2 = g_tmp3[g_csr_src[e + 2]];
        float v3 = g_tmp3[g_csr_src[e + 3]];
        a += (v0 + v1) + (v2 + v3);
    }
    for (; e < e1; e++) a += g_tmp3[g_csr_src[e]];
    float z = fmaf(g_dinv[n], a, b3[0]);
    out[n] = 1.0f / (1.0f + __expf(-z));
}

extern "C" void kernel_launch(void* const* d_in, const int* in_sizes, int n_in,
                              void* d_out, int out_size) {
    // Resolve inputs by element count — robust to metadata ordering.
    int ix = -1, ie = -1, iw1 = -1, iw2 = -1, ib3 = -1;
    int i32[3], n32 = 0;
    for (int i = 0; i < n_in; i++) {
        switch (in_sizes[i]) {
            case 19200000: ix = i; break;
            case 4800000:  ie = i; break;
            case 4096:     iw1 = i; break;
            case 1024:     iw2 = i; break;
            case 1:        ib3 = i; break;
            case 32:       if (n32 < 3) i32[n32++] = i; break;
            default: break;
        }
    }
    int ib1, ib2, iw3;
    if (ie == 1) {  // dict order: x, edge_index, W1, b1, W2, b2, W3, b3
        ib1 = i32[0]; ib2 = i32[1]; iw3 = i32[2];
    } else {        // alphabetical: W1, W2, W3, b1, b2, b3, edge_index, x
        iw3 = i32[0]; ib1 = i32[1]; ib2 = i32[2];
    }

    const float* x  = (const float*)d_in[ix];
    const int* ei   = (const int*)d_in[ie];   // [2, E] int32
    const float* W1 = (const float*)d_in[iw1];
    const float* b1 = (const float*)d_in[ib1];
    const float* W2 = (const float*)d_in[iw2];
    const float* b2 = (const float*)d_in[ib2];
    const float* W3 = (const float*)d_in[iw3];
    const float* b3 = (const float*)d_in[ib3];
    float* out = (float*)d_out;

    const int* src = ei;
    const int* dst = ei + N_EDGES;

    const int T = 256;
    int nblk_nodes = (N_NODES + T - 1) / T;
    int nblk_rows8 = (N_NODES + 7) / 8;

    // zero counters via memset node (graph-capturable)
    void* cnt_ptr = nullptr;
    cudaGetSymbolAddress(&cnt_ptr, g_cnt);
    cudaMemsetAsync(cnt_ptr, 0, N_NODES * sizeof(int), 0);

    // CSR build: pure hist, scans (dinv+cursor ready)
    k_hist<<<HIST_BLKS, T>>>(dst);
    k_scan_a<<<SCAN_NB, SCAN_BS>>>();
    k_scan_c<<<SCAN_NB, SCAN_BS>>>();   // fused scan_b + scan_c
    // F2: interleaved fill + xform1 (direct-gmem x, dinv-scaled inline)
    k_F2<<<EDGE_BLKS + X1_BLKS, T>>>(src, dst, x, W1);

    k_agg_xf2<<<nblk_rows8, T>>>(W2, b1);    // agg L1 + relu + @W2
    k_agg_xf3<<<nblk_rows8, T>>>(W3, b2);    // agg L2 + relu + dot W3
    k_agg1_final<<<nblk_nodes, T>>>(b3, out);
}

// round 11
// speedup vs baseline: 1.1161x; 1.1161x over previous
#include <cuda_runtime.h>
#include <cuda_fp16.h>
#include <math.h>

#define N_NODES 150000
#define N_EDGES 2400000
#define F_IN 128
#define HID 32
#define SCAN_BS 256
#define SCAN_NB ((N_NODES + SCAN_BS - 1) / SCAN_BS)   // 586

#define EDGE_BLKS 2344        // 600000 edge-quads / 256 (rounded up)
#define X1_BLKS 4688          // ceil(150000/32) rows, 32 rows/block
#define HIST_BLKS 1172        // 8 edges/thread

// Scratch (allocation-free rule: __device__ globals)
__device__ float  g_dinv[N_NODES];
__device__ __half g_tmp[(size_t)N_NODES * HID];    // fp16 messages (9.6 MB)
__device__ __half g_acc[(size_t)N_NODES * HID];
__device__ float  g_tmp3[N_NODES];
__device__ int    g_cnt[N_NODES];
__device__ int    g_rowptr[N_NODES + 1];
__device__ int    g_cursor[N_NODES];
__device__ int    g_bsum[1024];
__device__ int    g_csr_src[N_EDGES];

// ---------------- hist: 8 edges per thread ----------------
__global__ __launch_bounds__(256) void k_hist(const int* __restrict__ dst) {
    int t = blockIdx.x * blockDim.x + threadIdx.x;
    int q0 = t * 2;
    if (q0 < N_EDGES / 4) {
        int4 d = __ldg((const int4*)dst + q0);
        atomicAdd(&g_cnt[d.x], 1);
        atomicAdd(&g_cnt[d.y], 1);
        atomicAdd(&g_cnt[d.z], 1);
        atomicAdd(&g_cnt[d.w], 1);
    }
    if (q0 + 1 < N_EDGES / 4) {
        int4 d = __ldg((const int4*)dst + q0 + 1);
        atomicAdd(&g_cnt[d.x], 1);
        atomicAdd(&g_cnt[d.y], 1);
        atomicAdd(&g_cnt[d.z], 1);
        atomicAdd(&g_cnt[d.w], 1);
    }
}

// ---------------- scan A ----------------
__global__ void k_scan_a() {
    __shared__ int wsum[8];
    int tid = threadIdx.x;
    int lane = tid & 31, w = tid >> 5;
    int i = blockIdx.x * SCAN_BS + tid;
    int v = (i < N_NODES) ? g_cnt[i] : 0;
    int s = v;
#pragma unroll
    for (int o = 1; o < 32; o <<= 1) {
        int t = __shfl_up_sync(0xffffffffu, s, o);
        if (lane >= o) s += t;
    }
    if (lane == 31) wsum[w] = s;
    __syncthreads();
    if (w == 0 && lane < 8) {
        int ws = wsum[lane];
#pragma unroll
        for (int o = 1; o < 8; o <<= 1) {
            int t = __shfl_up_sync(0xffu, ws, o);
            if (lane >= o) ws += t;
        }
        wsum[lane] = ws;
    }
    __syncthreads();
    int incl = s + (w > 0 ? wsum[w - 1] : 0);
    if (i < N_NODES) g_rowptr[i] = incl - v;
    if (tid == SCAN_BS - 1) g_bsum[blockIdx.x] = incl;
}

// ---------------- scan C (fused B): each block sums bsum[0..blk) itself ----------------
__global__ void k_scan_c() {
    __shared__ int red[8];
    __shared__ int s_off;
    int tid = threadIdx.x;
    int lane = tid & 31, w = tid >> 5;
    int blk = blockIdx.x;
    int p = 0;
    for (int j = tid; j < blk; j += 256) p += g_bsum[j];
#pragma unroll
    for (int o = 16; o > 0; o >>= 1) p += __shfl_down_sync(0xffffffffu, p, o);
    if (lane == 0) red[w] = p;
    __syncthreads();
    if (tid == 0) {
        int t = 0;
#pragma unroll
        for (int k = 0; k < 8; k++) t += red[k];
        s_off = t;
    }
    __syncthreads();
    int off = s_off;
    int i = blk * 256 + tid;
    if (i < N_NODES) {
        int r = g_rowptr[i] + off;
        g_rowptr[i] = r;
        g_cursor[i] = r;
        g_dinv[i] = rsqrtf((float)(g_cnt[i] + 1));  // +1 self loop
    }
    if (i == 0) g_rowptr[N_NODES] = N_EDGES;
}

// ---------------- xform1 body: 32 rows/block, 4 rows/thread, dinv-scaled inline ----------------
__device__ __forceinline__ void xform1_body4(
    const float* __restrict__ x, const float* __restrict__ W1,
    float* sW, float* sx, int row0)
{
    int tid = threadIdx.x;
    {
        const float4* Wv = (const float4*)W1;
        float4* sWv = (float4*)sW;
#pragma unroll
        for (int i = 0; i < 4; i++) sWv[tid + i * 256] = Wv[tid + i * 256];
    }
    if (row0 + 32 <= N_NODES) {
        const float4* xv = (const float4*)(x + (size_t)row0 * F_IN);
        float4* sxv = (float4*)sx;
#pragma unroll
        for (int i = 0; i < 4; i++) sxv[tid + i * 256] = xv[tid + i * 256];
    } else {
        for (int i = tid; i < 32 * F_IN; i += 256) {
            int r = i >> 7;
            sx[i] = (row0 + r < N_NODES) ? x[(size_t)(row0 + r) * F_IN + (i & 127)] : 0.0f;
        }
    }
    __syncthreads();

    int w = tid >> 5, f = tid & 31;
    float acc0 = 0.f, acc1 = 0.f, acc2 = 0.f, acc3 = 0.f;
    const float* xr = &sx[(w * 4) * F_IN];
#pragma unroll
    for (int k4 = 0; k4 < F_IN; k4 += 4) {
        float w0 = sW[(k4 + 0) * HID + f];
        float w1 = sW[(k4 + 1) * HID + f];
        float w2 = sW[(k4 + 2) * HID + f];
        float w3 = sW[(k4 + 3) * HID + f];
        float4 xa = *(const float4*)(xr + 0 * F_IN + k4);
        float4 xb = *(const float4*)(xr + 1 * F_IN + k4);
        float4 xc = *(const float4*)(xr + 2 * F_IN + k4);
        float4 xd = *(const float4*)(xr + 3 * F_IN + k4);
        acc0 = fmaf(xa.x, w0, fmaf(xa.y, w1, fmaf(xa.z, w2, fmaf(xa.w, w3, acc0))));
        acc1 = fmaf(xb.x, w0, fmaf(xb.y, w1, fmaf(xb.z, w2, fmaf(xb.w, w3, acc1))));
        acc2 = fmaf(xc.x, w0, fmaf(xc.y, w1, fmaf(xc.z, w2, fmaf(xc.w, w3, acc2))));
        acc3 = fmaf(xd.x, w0, fmaf(xd.y, w1, fmaf(xd.z, w2, fmaf(xd.w, w3, acc3))));
    }
    float a[4] = {acc0, acc1, acc2, acc3};
#pragma unroll
    for (int r = 0; r < 4; r++) {
        int row = row0 + w * 4 + r;
        if (row < N_NODES)
            g_tmp[(size_t)row * HID + f] = __float2half_rn(g_dinv[row] * a[r]);
    }
}

// ---------------- F2: 1:2 interleaved fill + xform1 (32-row blocks, 32KB smem) ----------------
__global__ __launch_bounds__(256) void k_F2(const int* __restrict__ src,
                                            const int* __restrict__ dst,
                                            const float* __restrict__ x,
                                            const float* __restrict__ W1) {
    __shared__ __align__(16) float sW[F_IN * HID];   // 16 KB
    __shared__ __align__(16) float sx[32 * F_IN];    // 16 KB
    int grp = blockIdx.x / 3;
    int role = blockIdx.x - grp * 3;
    if (role == 0) {
        int t = grp * 256 + threadIdx.x;
        if (t < N_EDGES / 4) {
            int4 s = __ldg((const int4*)src + t);
            int4 d = __ldg((const int4*)dst + t);
            g_csr_src[atomicAdd(&g_cursor[d.x], 1)] = s.x;
            g_csr_src[atomicAdd(&g_cursor[d.y], 1)] = s.y;
            g_csr_src[atomicAdd(&g_cursor[d.z], 1)] = s.z;
            g_csr_src[atomicAdd(&g_cursor[d.w], 1)] = s.w;
        }
    } else {
        int xb = grp * 2 + (role - 1);       // 0 .. 4687
        xform1_body4(x, W1, sW, sx, xb * 32);
    }
}

// ---------------- fused: agg(L1) + relu + @W2 + scale -> g_acc (fp16) ----------------
// 4 edges per lane-group: lane = eidx*8 + fg; 8-edge unrolled main loop for MLP.
__global__ void k_agg_xf2(const float* __restrict__ W2, const float* __restrict__ b1) {
    __shared__ float sW[HID * HID];
    __shared__ float sy[8][HID];
    int tid = threadIdx.x;  // 256
    for (int i = tid; i < HID * HID; i += 256) sW[i] = W2[i];
    __syncthreads();
    int w = tid >> 5, lane = tid & 31;
    int n = blockIdx.x * 8 + w;
    if (n >= N_NODES) return;  // warp-uniform
    int eidx = lane >> 3, fg = lane & 7;
    int e = g_rowptr[n];
    int e1 = g_rowptr[n + 1];
    float ax = 0.f, ay = 0.f, az = 0.f, aw = 0.f;
    for (; e + 8 <= e1; e += 8) {
        int s0 = g_csr_src[e + eidx];
        int s1 = g_csr_src[e + 4 + eidx];
        int2 v0 = *(const int2*)(g_tmp + (size_t)s0 * HID + fg * 4);
        int2 v1 = *(const int2*)(g_tmp + (size_t)s1 * HID + fg * 4);
        float2 a0 = __half22float2(*(__half2*)&v0.x);
        float2 b0 = __half22float2(*(__half2*)&v0.y);
        float2 a1 = __half22float2(*(__half2*)&v1.x);
        float2 b1f = __half22float2(*(__half2*)&v1.y);
        ax += a0.x + a1.x; ay += a0.y + a1.y;
        az += b0.x + b1f.x; aw += b0.y + b1f.y;
    }
    if (e + 4 <= e1) {
        int s = g_csr_src[e + eidx];
        int2 v = *(const int2*)(g_tmp + (size_t)s * HID + fg * 4);
        float2 f0 = __half22float2(*(__half2*)&v.x);
        float2 f1 = __half22float2(*(__half2*)&v.y);
        ax += f0.x; ay += f0.y; az += f1.x; aw += f1.y;
        e += 4;
    }
    if (eidx < e1 - e) {
        int s = g_csr_src[e + eidx];
        int2 v = *(const int2*)(g_tmp + (size_t)s * HID + fg * 4);
        float2 f0 = __half22float2(*(__half2*)&v.x);
        float2 f1 = __half22float2(*(__half2*)&v.y);
        ax += f0.x; ay += f0.y; az += f1.x; aw += f1.y;
    }
#pragma unroll
    for (int o = 8; o <= 16; o <<= 1) {
        ax += __shfl_xor_sync(0xffffffffu, ax, o);
        ay += __shfl_xor_sync(0xffffffffu, ay, o);
        az += __shfl_xor_sync(0xffffffffu, az, o);
        aw += __shfl_xor_sync(0xffffffffu, aw, o);
    }
    // self loop
    {
        int2 v = *(const int2*)(g_tmp + (size_t)n * HID + fg * 4);
        float2 f0 = __half22float2(*(__half2*)&v.x);
        float2 f1 = __half22float2(*(__half2*)&v.y);
        ax += f0.x; ay += f0.y; az += f1.x; aw += f1.y;
    }
    float di = g_dinv[n];
    float4 bv = *(const float4*)(b1 + fg * 4);
    float4 y;
    y.x = fmaxf(fmaf(di, ax, bv.x), 0.0f);
    y.y = fmaxf(fmaf(di, ay, bv.y), 0.0f);
    y.z = fmaxf(fmaf(di, az, bv.z), 0.0f);
    y.w = fmaxf(fmaf(di, aw, bv.w), 0.0f);
    if (eidx == 0) *(float4*)&sy[w][fg * 4] = y;
    __syncwarp();
    float t = 0.0f;
#pragma unroll
    for (int k = 0; k < HID; k++) t = fmaf(sy[w][k], sW[k * HID + lane], t);
    g_acc[(size_t)n * HID + lane] = __float2half_rn(di * t);
}

// ---------------- fused: agg(L2) + relu + dot W3 + scale -> g_tmp3 ----------------
__global__ void k_agg_xf3(const float* __restrict__ W3, const float* __restrict__ b2) {
    int tid = threadIdx.x;
    int w = tid >> 5, lane = tid & 31;
    int n = blockIdx.x * 8 + w;
    if (n >= N_NODES) return;  // warp-uniform
    int eidx = lane >> 3, fg = lane & 7;
    int e = g_rowptr[n];
    int e1 = g_rowptr[n + 1];
    float ax = 0.f, ay = 0.f, az = 0.f, aw = 0.f;
    for (; e + 8 <= e1; e += 8) {
        int s0 = g_csr_src[e + eidx];
        int s1 = g_csr_src[e + 4 + eidx];
        int2 v0 = *(const int2*)(g_acc + (size_t)s0 * HID + fg * 4);
        int2 v1 = *(const int2*)(g_acc + (size_t)s1 * HID + fg * 4);
        float2 a0 = __half22float2(*(__half2*)&v0.x);
        float2 b0 = __half22float2(*(__half2*)&v0.y);
        float2 a1 = __half22float2(*(__half2*)&v1.x);
        float2 b1f = __half22float2(*(__half2*)&v1.y);
        ax += a0.x + a1.x; ay += a0.y + a1.y;
        az += b0.x + b1f.x; aw += b0.y + b1f.y;
    }
    if (e + 4 <= e1) {
        int s = g_csr_src[e + eidx];
        int2 v = *(const int2*)(g_acc + (size_t)s * HID + fg * 4);
        float2 f0 = __half22float2(*(__half2*)&v.x);
        float2 f1 = __half22float2(*(__half2*)&v.y);
        ax += f0.x; ay += f0.y; az += f1.x; aw += f1.y;
        e += 4;
    }
    if (eidx < e1 - e) {
        int s = g_csr_src[e + eidx];
        int2 v = *(const int2*)(g_acc + (size_t)s * HID + fg * 4);
        float2 f0 = __half22float2(*(__half2*)&v.x);
        float2 f1 = __half22float2(*(__half2*)&v.y);
        ax += f0.x; ay += f0.y; az += f1.x; aw += f1.y;
    }
#pragma unroll
    for (int o = 8; o <= 16; o <<= 1) {
        ax += __shfl_xor_sync(0xffffffffu, ax, o);
        ay += __shfl_xor_sync(0xffffffffu, ay, o);
        az += __shfl_xor_sync(0xffffffffu, az, o);
        aw += __shfl_xor_sync(0xffffffffu, aw, o);
    }
    {
        int2 v = *(const int2*)(g_acc + (size_t)n * HID + fg * 4);
        float2 f0 = __half22float2(*(__half2*)&v.x);
        float2 f1 = __half22float2(*(__half2*)&v.y);
        ax += f0.x; ay += f0.y; az += f1.x; aw += f1.y;
    }
    float di = g_dinv[n];
    float4 bv = *(const float4*)(b2 + fg * 4);
    float4 wv = *(const float4*)(W3 + fg * 4);
    float t = fmaxf(fmaf(di, ax, bv.x), 0.0f) * wv.x
            + fmaxf(fmaf(di, ay, bv.y), 0.0f) * wv.y
            + fmaxf(fmaf(di, az, bv.z), 0.0f) * wv.z
            + fmaxf(fmaf(di, aw, bv.w), 0.0f) * wv.w;
#pragma unroll
    for (int o = 1; o <= 4; o <<= 1) t += __shfl_xor_sync(0xffffffffu, t, o);
    if (lane == 0) g_tmp3[n] = di * t;
}

// ---------------- scalar gather + final sigmoid ----------------
__global__ void k_agg1_final(const float* __restrict__ b3, float* __restrict__ out) {
    int n = blockIdx.x * blockDim.x + threadIdx.x;
    if (n >= N_NODES) return;
    int e = g_rowptr[n];
    int e1 = g_rowptr[n + 1];
    float a = g_tmp3[n];  // self loop
    for (; e + 4 <= e1; e += 4) {
        float v0 = g_tmp3[g_csr_src[e + 0]];
        float v1 = g_tmp3[g_csr_src[e + 1]];
        float v2 = g_tmp3[g_csr_src[e + 2]];
        float v3 = g_tmp3[g_csr_src[e + 3]];
        a += (v0 + v1) + (v2 + v3);
    }
    for (; e < e1; e++) a += g_tmp3[g_csr_src[e]];
    float z = fmaf(g_dinv[n], a, b3[0]);
    out[n] = 1.0f / (1.0f + __expf(-z));
}

extern "C" void kernel_launch(void* const* d_in, const int* in_sizes, int n_in,
                              void* d_out, int out_size) {
    // Resolve inputs by element count — robust to metadata ordering.
    int ix = -1, ie = -1, iw1 = -1, iw2 = -1, ib3 = -1;
    int i32[3], n32 = 0;
    for (int i = 0; i < n_in; i++) {
        switch (in_sizes[i]) {
            case 19200000: ix = i; break;
            case 4800000:  ie = i; break;
            case 4096:     iw1 = i; break;
            case 1024:     iw2 = i; break;
            case 1:        ib3 = i; break;
            case 32:       if (n32 < 3) i32[n32++] = i; break;
            default: break;
        }
    }
    int ib1, ib2, iw3;
    if (ie == 1) {  // dict order: x, edge_index, W1, b1, W2, b2, W3, b3
        ib1 = i32[0]; ib2 = i32[1]; iw3 = i32[2];
    } else {        // alphabetical: W1, W2, W3, b1, b2, b3, edge_index, x
        iw3 = i32[0]; ib1 = i32[1]; ib2 = i32[2];
    }

    const float* x  = (const float*)d_in[ix];
    const int* ei   = (const int*)d_in[ie];   // [2, E] int32
    const float* W1 = (const float*)d_in[iw1];
    const float* b1 = (const float*)d_in[ib1];
    const float* W2 = (const float*)d_in[iw2];
    const float* b2 = (const float*)d_in[ib2];
    const float* W3 = (const float*)d_in[iw3];
    const float* b3 = (const float*)d_in[ib3];
    float* out = (float*)d_out;

    const int* src = ei;
    const int* dst = ei + N_EDGES;

    const int T = 256;
    int nblk_nodes = (N_NODES + T - 1) / T;
    int nblk_rows8 = (N_NODES + 7) / 8;

    // zero counters via memset node (graph-capturable)
    void* cnt_ptr = nullptr;
    cudaGetSymbolAddress(&cnt_ptr, g_cnt);
    cudaMemsetAsync(cnt_ptr, 0, N_NODES * sizeof(int), 0);

    // CSR build: pure hist, scans (dinv+cursor ready)
    k_hist<<<HIST_BLKS, T>>>(dst);
    k_scan_a<<<SCAN_NB, SCAN_BS>>>();
    k_scan_c<<<SCAN_NB, SCAN_BS>>>();   // fused scan_b + scan_c
    // F2: 1:2 interleaved fill + xform1 (32-row blocks, dinv-scaled inline)
    k_F2<<<3 * EDGE_BLKS, T>>>(src, dst, x, W1);

    k_agg_xf2<<<nblk_rows8, T>>>(W2, b1);    // agg L1 + relu + @W2
    k_agg_xf3<<<nblk_rows8, T>>>(W3, b2);    // agg L2 + relu + dot W3
    k_agg1_final<<<nblk_nodes, T>>>(b3, out);
}

// round 13
// speedup vs baseline: 1.1505x; 1.0308x over previous
#include <cuda_runtime.h>
#include <cuda_fp16.h>
#include <mma.h>
#include <math.h>

using namespace nvcuda;

#define N_NODES 150000
#define N_EDGES 2400000
#define F_IN 128
#define HID 32
#define SCAN_BS 256
#define SCAN_NB ((N_NODES + SCAN_BS - 1) / SCAN_BS)   // 586

#define EDGE_BLKS 2344        // 600000 edge-quads / 256 (rounded up)
#define X1_BLKS 2344          // ceil(150000/64), 64 rows/block (tensor core)
#define HIST_BLKS 1172        // 8 edges/thread

#define SX_STRIDE 136         // padded half stride (8-half aligned, conflict-spread)

// Scratch (allocation-free rule: __device__ globals)
__device__ float  g_dinv[N_NODES];
__device__ __half g_tmp[(size_t)N_NODES * HID];    // fp16 messages (9.6 MB)
__device__ __half g_acc[(size_t)N_NODES * HID];
__device__ float  g_tmp3[N_NODES];
__device__ int    g_cnt[N_NODES];
__device__ int    g_rowptr[N_NODES + 1];
__device__ int    g_cursor[N_NODES];
__device__ int    g_bsum[1024];
__device__ int    g_csr_src[N_EDGES];

// ---------------- hist: 8 edges per thread ----------------
__global__ __launch_bounds__(256) void k_hist(const int* __restrict__ dst) {
    int t = blockIdx.x * blockDim.x + threadIdx.x;
    int q0 = t * 2;
    if (q0 < N_EDGES / 4) {
        int4 d = __ldg((const int4*)dst + q0);
        atomicAdd(&g_cnt[d.x], 1);
        atomicAdd(&g_cnt[d.y], 1);
        atomicAdd(&g_cnt[d.z], 1);
        atomicAdd(&g_cnt[d.w], 1);
    }
    if (q0 + 1 < N_EDGES / 4) {
        int4 d = __ldg((const int4*)dst + q0 + 1);
        atomicAdd(&g_cnt[d.x], 1);
        atomicAdd(&g_cnt[d.y], 1);
        atomicAdd(&g_cnt[d.z], 1);
        atomicAdd(&g_cnt[d.w], 1);
    }
}

// ---------------- scan A ----------------
__global__ void k_scan_a() {
    __shared__ int wsum[8];
    int tid = threadIdx.x;
    int lane = tid & 31, w = tid >> 5;
    int i = blockIdx.x * SCAN_BS + tid;
    int v = (i < N_NODES) ? g_cnt[i] : 0;
    int s = v;
#pragma unroll
    for (int o = 1; o < 32; o <<= 1) {
        int t = __shfl_up_sync(0xffffffffu, s, o);
        if (lane >= o) s += t;
    }
    if (lane == 31) wsum[w] = s;
    __syncthreads();
    if (w == 0 && lane < 8) {
        int ws = wsum[lane];
#pragma unroll
        for (int o = 1; o < 8; o <<= 1) {
            int t = __shfl_up_sync(0xffu, ws, o);
            if (lane >= o) ws += t;
        }
        wsum[lane] = ws;
    }
    __syncthreads();
    int incl = s + (w > 0 ? wsum[w - 1] : 0);
    if (i < N_NODES) g_rowptr[i] = incl - v;
    if (tid == SCAN_BS - 1) g_bsum[blockIdx.x] = incl;
}

// ---------------- scan C (fused B): each block sums bsum[0..blk) itself ----------------
__global__ void k_scan_c() {
    __shared__ int red[8];
    __shared__ int s_off;
    int tid = threadIdx.x;
    int lane = tid & 31, w = tid >> 5;
    int blk = blockIdx.x;
    int p = 0;
    for (int j = tid; j < blk; j += 256) p += g_bsum[j];
#pragma unroll
    for (int o = 16; o > 0; o >>= 1) p += __shfl_down_sync(0xffffffffu, p, o);
    if (lane == 0) red[w] = p;
    __syncthreads();
    if (tid == 0) {
        int t = 0;
#pragma unroll
        for (int k = 0; k < 8; k++) t += red[k];
        s_off = t;
    }
    __syncthreads();
    int off = s_off;
    int i = blk * 256 + tid;
    if (i < N_NODES) {
        int r = g_rowptr[i] + off;
        g_rowptr[i] = r;
        g_cursor[i] = r;
        g_dinv[i] = rsqrtf((float)(g_cnt[i] + 1));  // +1 self loop
    }
    if (i == 0) g_rowptr[N_NODES] = N_EDGES;
}

// ---------------- F2: interleaved fill (even) + wmma xform1 (odd) ----------------
// xform block: 64 rows. x fp32->fp16 smem (padded), W1^T fp16 smem [n][k],
// wmma 16x16x16 fp32-accum; epilogue scales by dinv, stores fp16.
__global__ __launch_bounds__(256) void k_F2(const int* __restrict__ src,
                                            const int* __restrict__ dst,
                                            const float* __restrict__ x,
                                            const float* __restrict__ W1) {
    __shared__ __half sX[64 * SX_STRIDE];    // 17408 B
    __shared__ __half sWt[32 * SX_STRIDE];   // 8704 B
    __shared__ float  sC[8 * 256];           // 8192 B
    int tid = threadIdx.x;
    int half_idx = blockIdx.x >> 1;
    if ((blockIdx.x & 1) == 0) {
        int t = half_idx * 256 + tid;
        if (t < N_EDGES / 4) {
            int4 s = __ldg((const int4*)src + t);
            int4 d = __ldg((const int4*)dst + t);
            g_csr_src[atomicAdd(&g_cursor[d.x], 1)] = s.x;
            g_csr_src[atomicAdd(&g_cursor[d.y], 1)] = s.y;
            g_csr_src[atomicAdd(&g_cursor[d.z], 1)] = s.z;
            g_csr_src[atomicAdd(&g_cursor[d.w], 1)] = s.w;
        }
        return;
    }
    int row0 = half_idx * 64;
    // stage x tile (fp32 -> fp16), zero-fill OOB rows
    {
        const float4* xv = (const float4*)(x + (size_t)row0 * F_IN);
#pragma unroll
        for (int i = 0; i < 8; i++) {
            int idx = tid + i * 256;          // 0..2047
            int r = idx >> 5;                 // row in tile
            int c = idx & 31;                 // float4 column
            float4 v = make_float4(0.f, 0.f, 0.f, 0.f);
            if (row0 + r < N_NODES) v = __ldg(xv + idx);
            int off = r * SX_STRIDE + c * 4;
            *(__half2*)&sX[off]     = __floats2half2_rn(v.x, v.y);
            *(__half2*)&sX[off + 2] = __floats2half2_rn(v.z, v.w);
        }
    }
    // stage W1^T: sWt[n][k] = W1[k][n]
    for (int i = tid; i < F_IN * HID; i += 256) {
        int k = i >> 5;
        int n = i & 31;
        sWt[n * SX_STRIDE + k] = __float2half_rn(W1[i]);
    }
    __syncthreads();

    int w = tid >> 5, l = tid & 31;
    int m0 = (w & 3) * 16;        // warp's row tile within the 64-row block
    int n0 = (w >> 2) * 16;       // warp's col tile (0 or 16)

    wmma::fragment<wmma::matrix_a, 16, 16, 16, __half, wmma::row_major> afrag;
    wmma::fragment<wmma::matrix_b, 16, 16, 16, __half, wmma::col_major> bfrag;
    wmma::fragment<wmma::accumulator, 16, 16, 16, float> cfrag;
    wmma::fill_fragment(cfrag, 0.0f);
#pragma unroll
    for (int ks = 0; ks < 8; ks++) {
        wmma::load_matrix_sync(afrag, &sX[m0 * SX_STRIDE + ks * 16], SX_STRIDE);
        wmma::load_matrix_sync(bfrag, &sWt[n0 * SX_STRIDE + ks * 16], SX_STRIDE);
        wmma::mma_sync(cfrag, afrag, bfrag, cfrag);
    }
    wmma::store_matrix_sync(&sC[w * 256], cfrag, 16, wmma::mem_row_major);
    __syncwarp();
    // epilogue: scale by dinv, convert, store fp16 (half2 per lane-iter)
    for (int idx = l; idx < 128; idx += 32) {
        int r = idx >> 3;            // 0..15
        int c = (idx & 7) * 2;       // 0,2,..,14
        int row = row0 + m0 + r;
        if (row < N_NODES) {
            float di = g_dinv[row];
            float v0 = sC[w * 256 + r * 16 + c];
            float v1 = sC[w * 256 + r * 16 + c + 1];
            *(__half2*)&g_tmp[(size_t)row * HID + n0 + c] =
                __floats2half2_rn(di * v0, di * v1);
        }
    }
}

// ---------------- fused: agg(L1) + relu + @W2 + scale -> g_acc (fp16) ----------------
// 4 edges per lane-group: lane = eidx*8 + fg; 8-edge unrolled main loop for MLP.
__global__ void k_agg_xf2(const float* __restrict__ W2, const float* __restrict__ b1) {
    __shared__ float sW[HID * HID];
    __shared__ float sy[8][HID];
    int tid = threadIdx.x;  // 256
    for (int i = tid; i < HID * HID; i += 256) sW[i] = W2[i];
    __syncthreads();
    int w = tid >> 5, lane = tid & 31;
    int n = blockIdx.x * 8 + w;
    if (n >= N_NODES) return;  // warp-uniform
    int eidx = lane >> 3, fg = lane & 7;
    int e = g_rowptr[n];
    int e1 = g_rowptr[n + 1];
    float ax = 0.f, ay = 0.f, az = 0.f, aw = 0.f;
    for (; e + 8 <= e1; e += 8) {
        int s0 = g_csr_src[e + eidx];
        int s1 = g_csr_src[e + 4 + eidx];
        int2 v0 = *(const int2*)(g_tmp + (size_t)s0 * HID + fg * 4);
        int2 v1 = *(const int2*)(g_tmp + (size_t)s1 * HID + fg * 4);
        float2 a0 = __half22float2(*(__half2*)&v0.x);
        float2 b0 = __half22float2(*(__half2*)&v0.y);
        float2 a1 = __half22float2(*(__half2*)&v1.x);
        float2 b1f = __half22float2(*(__half2*)&v1.y);
        ax += a0.x + a1.x; ay += a0.y + a1.y;
        az += b0.x + b1f.x; aw += b0.y + b1f.y;
    }
    if (e + 4 <= e1) {
        int s = g_csr_src[e + eidx];
        int2 v = *(const int2*)(g_tmp + (size_t)s * HID + fg * 4);
        float2 f0 = __half22float2(*(__half2*)&v.x);
        float2 f1 = __half22float2(*(__half2*)&v.y);
        ax += f0.x; ay += f0.y; az += f1.x; aw += f1.y;
        e += 4;
    }
    if (eidx < e1 - e) {
        int s = g_csr_src[e + eidx];
        int2 v = *(const int2*)(g_tmp + (size_t)s * HID + fg * 4);
        float2 f0 = __half22float2(*(__half2*)&v.x);
        float2 f1 = __half22float2(*(__half2*)&v.y);
        ax += f0.x; ay += f0.y; az += f1.x; aw += f1.y;
    }
#pragma unroll
    for (int o = 8; o <= 16; o <<= 1) {
        ax += __shfl_xor_sync(0xffffffffu, ax, o);
        ay += __shfl_xor_sync(0xffffffffu, ay, o);
        az += __shfl_xor_sync(0xffffffffu, az, o);
        aw += __shfl_xor_sync(0xffffffffu, aw, o);
    }
    // self loop
    {
        int2 v = *(const int2*)(g_tmp + (size_t)n * HID + fg * 4);
        float2 f0 = __half22float2(*(__half2*)&v.x);
        float2 f1 = __half22float2(*(__half2*)&v.y);
        ax += f0.x; ay += f0.y; az += f1.x; aw += f1.y;
    }
    float di = g_dinv[n];
    float4 bv = *(const float4*)(b1 + fg * 4);
    float4 y;
    y.x = fmaxf(fmaf(di, ax, bv.x), 0.0f);
    y.y = fmaxf(fmaf(di, ay, bv.y), 0.0f);
    y.z = fmaxf(fmaf(di, az, bv.z), 0.0f);
    y.w = fmaxf(fmaf(di, aw, bv.w), 0.0f);
    if (eidx == 0) *(float4*)&sy[w][fg * 4] = y;
    __syncwarp();
    float t = 0.0f;
#pragma unroll
    for (int k = 0; k < HID; k++) t = fmaf(sy[w][k], sW[k * HID + lane], t);
    g_acc[(size_t)n * HID + lane] = __float2half_rn(di * t);
}

// ---------------- fused: agg(L2) + relu + dot W3 + scale -> g_tmp3 ----------------
__global__ void k_agg_xf3(const float* __restrict__ W3, const float* __restrict__ b2) {
    int tid = threadIdx.x;
    int w = tid >> 5, lane = tid & 31;
    int n = blockIdx.x * 8 + w;
    if (n >= N_NODES) return;  // warp-uniform
    int eidx = lane >> 3, fg = lane & 7;
    int e = g_rowptr[n];
    int e1 = g_rowptr[n + 1];
    float ax = 0.f, ay = 0.f, az = 0.f, aw = 0.f;
    for (; e + 8 <= e1; e += 8) {
        int s0 = g_csr_src[e + eidx];
        int s1 = g_csr_src[e + 4 + eidx];
        int2 v0 = *(const int2*)(g_acc + (size_t)s0 * HID + fg * 4);
        int2 v1 = *(const int2*)(g_acc + (size_t)s1 * HID + fg * 4);
        float2 a0 = __half22float2(*(__half2*)&v0.x);
        float2 b0 = __half22float2(*(__half2*)&v0.y);
        float2 a1 = __half22float2(*(__half2*)&v1.x);
        float2 b1f = __half22float2(*(__half2*)&v1.y);
        ax += a0.x + a1.x; ay += a0.y + a1.y;
        az += b0.x + b1f.x; aw += b0.y + b1f.y;
    }
    if (e + 4 <= e1) {
        int s = g_csr_src[e + eidx];
        int2 v = *(const int2*)(g_acc + (size_t)s * HID + fg * 4);
        float2 f0 = __half22float2(*(__half2*)&v.x);
        float2 f1 = __half22float2(*(__half2*)&v.y);
        ax += f0.x; ay += f0.y; az += f1.x; aw += f1.y;
        e += 4;
    }
    if (eidx < e1 - e) {
        int s = g_csr_src[e + eidx];
        int2 v = *(const int2*)(g_acc + (size_t)s * HID + fg * 4);
        float2 f0 = __half22float2(*(__half2*)&v.x);
        float2 f1 = __half22float2(*(__half2*)&v.y);
        ax += f0.x; ay += f0.y; az += f1.x; aw += f1.y;
    }
#pragma unroll
    for (int o = 8; o <= 16; o <<= 1) {
        ax += __shfl_xor_sync(0xffffffffu, ax, o);
        ay += __shfl_xor_sync(0xffffffffu, ay, o);
        az += __shfl_xor_sync(0xffffffffu, az, o);
        aw += __shfl_xor_sync(0xffffffffu, aw, o);
    }
    {
        int2 v = *(const int2*)(g_acc + (size_t)n * HID + fg * 4);
        float2 f0 = __half22float2(*(__half2*)&v.x);
        float2 f1 = __half22float2(*(__half2*)&v.y);
        ax += f0.x; ay += f0.y; az += f1.x; aw += f1.y;
    }
    float di = g_dinv[n];
    float4 bv = *(const float4*)(b2 + fg * 4);
    float4 wv = *(const float4*)(W3 + fg * 4);
    float t = fmaxf(fmaf(di, ax, bv.x), 0.0f) * wv.x
            + fmaxf(fmaf(di, ay, bv.y), 0.0f) * wv.y
            + fmaxf(fmaf(di, az, bv.z), 0.0f) * wv.z
            + fmaxf(fmaf(di, aw, bv.w), 0.0f) * wv.w;
#pragma unroll
    for (int o = 1; o <= 4; o <<= 1) t += __shfl_xor_sync(0xffffffffu, t, o);
    if (lane == 0) g_tmp3[n] = di * t;
}

// ---------------- scalar gather + final sigmoid ----------------
__global__ void k_agg1_final(const float* __restrict__ b3, float* __restrict__ out) {
    int n = blockIdx.x * blockDim.x + threadIdx.x;
    if (n >= N_NODES) return;
    int e = g_rowptr[n];
    int e1 = g_rowptr[n + 1];
    float a = g_tmp3[n];  // self loop
    for (; e + 4 <= e1; e += 4) {
        float v0 = g_tmp3[g_csr_src[e + 0]];
        float v1 = g_tmp3[g_csr_src[e + 1]];
        float v2 = g_tmp3[g_csr_src[e + 2]];
        float v3 = g_tmp3[g_csr_src[e + 3]];
        a += (v0 + v1) + (v2 + v3);
    }
    for (; e < e1; e++) a += g_tmp3[g_csr_src[e]];
    float z = fmaf(g_dinv[n], a, b3[0]);
    out[n] = 1.0f / (1.0f + __expf(-z));
}

extern "C" void kernel_launch(void* const* d_in, const int* in_sizes, int n_in,
                              void* d_out, int out_size) {
    // Resolve inputs by element count — robust to metadata ordering.
    int ix = -1, ie = -1, iw1 = -1, iw2 = -1, ib3 = -1;
    int i32[3], n32 = 0;
    for (int i = 0; i < n_in; i++) {
        switch (in_sizes[i]) {
            case 19200000: ix = i; break;
            case 4800000:  ie = i; break;
            case 4096:     iw1 = i; break;
            case 1024:     iw2 = i; break;
            case 1:        ib3 = i; break;
            case 32:       if (n32 < 3) i32[n32++] = i; break;
            default: break;
        }
    }
    int ib1, ib2, iw3;
    if (ie == 1) {  // dict order: x, edge_index, W1, b1, W2, b2, W3, b3
        ib1 = i32[0]; ib2 = i32[1]; iw3 = i32[2];
    } else {        // alphabetical: W1, W2, W3, b1, b2, b3, edge_index, x
        iw3 = i32[0]; ib1 = i32[1]; ib2 = i32[2];
    }

    const float* x  = (const float*)d_in[ix];
    const int* ei   = (const int*)d_in[ie];   // [2, E] int32
    const float* W1 = (const float*)d_in[iw1];
    const float* b1 = (const float*)d_in[ib1];
    const float* W2 = (const float*)d_in[iw2];
    const float* b2 = (const float*)d_in[ib2];
    const float* W3 = (const float*)d_in[iw3];
    const float* b3 = (const float*)d_in[ib3];
    float* out = (float*)d_out;

    const int* src = ei;
    const int* dst = ei + N_EDGES;

    const int T = 256;
    int nblk_nodes = (N_NODES + T - 1) / T;
    int nblk_rows8 = (N_NODES + 7) / 8;

    // zero counters via memset node (graph-capturable)
    void* cnt_ptr = nullptr;
    cudaGetSymbolAddress(&cnt_ptr, g_cnt);
    cudaMemsetAsync(cnt_ptr, 0, N_NODES * sizeof(int), 0);

    // CSR build: pure hist, scans (dinv+cursor ready)
    k_hist<<<HIST_BLKS, T>>>(dst);
    k_scan_a<<<SCAN_NB, SCAN_BS>>>();
    k_scan_c<<<SCAN_NB, SCAN_BS>>>();   // fused scan_b + scan_c
    // F2: interleaved fill + wmma xform1 (fp16 in / fp32 acc, dinv inline)
    k_F2<<<EDGE_BLKS + X1_BLKS, T>>>(src, dst, x, W1);

    k_agg_xf2<<<nblk_rows8, T>>>(W2, b1);    // agg L1 + relu + @W2
    k_agg_xf3<<<nblk_rows8, T>>>(W3, b2);    // agg L2 + relu + dot W3
    k_agg1_final<<<nblk_nodes, T>>>(b3, out);
}

// round 14
// speedup vs baseline: 1.2697x; 1.1036x over previous
#include <cuda_runtime.h>
#include <cuda_fp16.h>
#include <mma.h>
#include <math.h>

using namespace nvcuda;

#define N_NODES 150000
#define N_EDGES 2400000
#define F_IN 128
#define HID 32
#define SCAN_BS 256
#define SCAN_NB ((N_NODES + SCAN_BS - 1) / SCAN_BS)   // 586

#define EDGE_BLKS 2344        // 600000 edge-quads / 256 (rounded up)
#define X1_BLKS 2344          // ceil(150000/64), 64 rows/block (tensor core)
#define HIST_BLKS 1172        // 8 edges/thread
#define SCALE_BLKS 2344       // 600000 int4 / 256

#define SX_STRIDE 136         // padded half stride

// Scratch (allocation-free rule: __device__ globals)
__device__ float  g_dinv[N_NODES];
__device__ __half g_tmp[(size_t)N_NODES * HID];    // fp16 messages (9.6 MB)
__device__ __half g_acc[(size_t)N_NODES * HID];
__device__ float  g_tmp3[N_NODES];
__device__ int    g_cnt[N_NODES];
__device__ int    g_rowptr[N_NODES + 1];
__device__ int    g_cursor[N_NODES];
__device__ int    g_bsum[1024];
__device__ int    g_csr_src[N_EDGES];

// ---------------- F1: hist (role 0) + wmma xform1 RAW (roles 1,2) ----------------
__global__ __launch_bounds__(256) void k_F1(const int* __restrict__ dst,
                                            const float* __restrict__ x,
                                            const float* __restrict__ W1) {
    __shared__ __half sX[64 * SX_STRIDE];    // 17408 B
    __shared__ __half sWt[32 * SX_STRIDE];   // 8704 B
    __shared__ float  sC[8 * 256];           // 8192 B
    int tid = threadIdx.x;
    int grp = blockIdx.x / 3;
    int role = blockIdx.x - grp * 3;
    if (role == 0) {
        // hist: 8 edges per thread, block index grp in [0, HIST_BLKS)
        int t = grp * 256 + tid;
        int q0 = t * 2;
        if (q0 < N_EDGES / 4) {
            int4 d = __ldg((const int4*)dst + q0);
            atomicAdd(&g_cnt[d.x], 1);
            atomicAdd(&g_cnt[d.y], 1);
            atomicAdd(&g_cnt[d.z], 1);
            atomicAdd(&g_cnt[d.w], 1);
        }
        if (q0 + 1 < N_EDGES / 4) {
            int4 d = __ldg((const int4*)dst + q0 + 1);
            atomicAdd(&g_cnt[d.x], 1);
            atomicAdd(&g_cnt[d.y], 1);
            atomicAdd(&g_cnt[d.z], 1);
            atomicAdd(&g_cnt[d.w], 1);
        }
        return;
    }
    int xb = grp * 2 + (role - 1);    // xform tile in [0, X1_BLKS)
    int row0 = xb * 64;
    // stage x tile (fp32 -> fp16), zero-fill OOB rows
    {
        const float4* xv = (const float4*)(x + (size_t)row0 * F_IN);
#pragma unroll
        for (int i = 0; i < 8; i++) {
            int idx = tid + i * 256;          // 0..2047
            int r = idx >> 5;
            int c = idx & 31;
            float4 v = make_float4(0.f, 0.f, 0.f, 0.f);
            if (row0 + r < N_NODES) v = __ldg(xv + idx);
            int off = r * SX_STRIDE + c * 4;
            *(__half2*)&sX[off]     = __floats2half2_rn(v.x, v.y);
            *(__half2*)&sX[off + 2] = __floats2half2_rn(v.z, v.w);
        }
    }
    // stage W1^T: sWt[n][k] = W1[k][n]
    for (int i = tid; i < F_IN * HID; i += 256) {
        int k = i >> 5;
        int n = i & 31;
        sWt[n * SX_STRIDE + k] = __float2half_rn(W1[i]);
    }
    __syncthreads();

    int w = tid >> 5, l = tid & 31;
    int m0 = (w & 3) * 16;
    int n0 = (w >> 2) * 16;

    wmma::fragment<wmma::matrix_a, 16, 16, 16, __half, wmma::row_major> afrag;
    wmma::fragment<wmma::matrix_b, 16, 16, 16, __half, wmma::col_major> bfrag;
    wmma::fragment<wmma::accumulator, 16, 16, 16, float> cfrag;
    wmma::fill_fragment(cfrag, 0.0f);
#pragma unroll
    for (int ks = 0; ks < 8; ks++) {
        wmma::load_matrix_sync(afrag, &sX[m0 * SX_STRIDE + ks * 16], SX_STRIDE);
        wmma::load_matrix_sync(bfrag, &sWt[n0 * SX_STRIDE + ks * 16], SX_STRIDE);
        wmma::mma_sync(cfrag, afrag, bfrag, cfrag);
    }
    wmma::store_matrix_sync(&sC[w * 256], cfrag, 16, wmma::mem_row_major);
    __syncwarp();
    // epilogue: store RAW fp16 (dinv applied later in F2 scale pass)
    for (int idx = l; idx < 128; idx += 32) {
        int r = idx >> 3;
        int c = (idx & 7) * 2;
        int row = row0 + m0 + r;
        if (row < N_NODES) {
            float v0 = sC[w * 256 + r * 16 + c];
            float v1 = sC[w * 256 + r * 16 + c + 1];
            *(__half2*)&g_tmp[(size_t)row * HID + n0 + c] = __floats2half2_rn(v0, v1);
        }
    }
}

// ---------------- scan A ----------------
__global__ void k_scan_a() {
    __shared__ int wsum[8];
    int tid = threadIdx.x;
    int lane = tid & 31, w = tid >> 5;
    int i = blockIdx.x * SCAN_BS + tid;
    int v = (i < N_NODES) ? g_cnt[i] : 0;
    int s = v;
#pragma unroll
    for (int o = 1; o < 32; o <<= 1) {
        int t = __shfl_up_sync(0xffffffffu, s, o);
        if (lane >= o) s += t;
    }
    if (lane == 31) wsum[w] = s;
    __syncthreads();
    if (w == 0 && lane < 8) {
        int ws = wsum[lane];
#pragma unroll
        for (int o = 1; o < 8; o <<= 1) {
            int t = __shfl_up_sync(0xffu, ws, o);
            if (lane >= o) ws += t;
        }
        wsum[lane] = ws;
    }
    __syncthreads();
    int incl = s + (w > 0 ? wsum[w - 1] : 0);
    if (i < N_NODES) g_rowptr[i] = incl - v;
    if (tid == SCAN_BS - 1) g_bsum[blockIdx.x] = incl;
}

// ---------------- scan C (fused B): each block sums bsum[0..blk) itself ----------------
__global__ void k_scan_c() {
    __shared__ int red[8];
    __shared__ int s_off;
    int tid = threadIdx.x;
    int lane = tid & 31, w = tid >> 5;
    int blk = blockIdx.x;
    int p = 0;
    for (int j = tid; j < blk; j += 256) p += g_bsum[j];
#pragma unroll
    for (int o = 16; o > 0; o >>= 1) p += __shfl_down_sync(0xffffffffu, p, o);
    if (lane == 0) red[w] = p;
    __syncthreads();
    if (tid == 0) {
        int t = 0;
#pragma unroll
        for (int k = 0; k < 8; k++) t += red[k];
        s_off = t;
    }
    __syncthreads();
    int off = s_off;
    int i = blk * 256 + tid;
    if (i < N_NODES) {
        int r = g_rowptr[i] + off;
        g_rowptr[i] = r;
        g_cursor[i] = r;
        g_dinv[i] = rsqrtf((float)(g_cnt[i] + 1));  // +1 self loop
    }
    if (i == 0) g_rowptr[N_NODES] = N_EDGES;
}

// ---------------- F2: interleaved fill (even) + dinv-scale of g_tmp (odd) ----------------
__global__ __launch_bounds__(256) void k_F2(const int* __restrict__ src,
                                            const int* __restrict__ dst) {
    int tid = threadIdx.x;
    int half_idx = blockIdx.x >> 1;
    if ((blockIdx.x & 1) == 0) {
        int t = half_idx * 256 + tid;
        if (t < N_EDGES / 4) {
            int4 s = __ldg((const int4*)src + t);
            int4 d = __ldg((const int4*)dst + t);
            g_csr_src[atomicAdd(&g_cursor[d.x], 1)] = s.x;
            g_csr_src[atomicAdd(&g_cursor[d.y], 1)] = s.y;
            g_csr_src[atomicAdd(&g_cursor[d.z], 1)] = s.z;
            g_csr_src[atomicAdd(&g_cursor[d.w], 1)] = s.w;
        }
    } else {
        int i = half_idx * 256 + tid;   // int4 index: 8 halves per thread
        if (i < 600000) {
            int4* tv = (int4*)g_tmp;
            int4 raw = tv[i];
            float di = g_dinv[i >> 2];  // 4 int4 per 32-half row
            __half2* h = (__half2*)&raw;
            __half2 d2 = __float2half2_rn(di);
#pragma unroll
            for (int k = 0; k < 4; k++) h[k] = __hmul2(h[k], d2);
            tv[i] = raw;
        }
    }
}

// ---------------- fused: agg(L1) + relu + @W2 + scale -> g_acc (fp16) ----------------
__global__ void k_agg_xf2(const float* __restrict__ W2, const float* __restrict__ b1) {
    __shared__ float sW[HID * HID];
    __shared__ float sy[8][HID];
    int tid = threadIdx.x;  // 256
    for (int i = tid; i < HID * HID; i += 256) sW[i] = W2[i];
    __syncthreads();
    int w = tid >> 5, lane = tid & 31;
    int n = blockIdx.x * 8 + w;
    if (n >= N_NODES) return;  // warp-uniform
    int eidx = lane >> 3, fg = lane & 7;
    int e = g_rowptr[n];
    int e1 = g_rowptr[n + 1];
    float ax = 0.f, ay = 0.f, az = 0.f, aw = 0.f;
    for (; e + 8 <= e1; e += 8) {
        int s0 = g_csr_src[e + eidx];
        int s1 = g_csr_src[e + 4 + eidx];
        int2 v0 = *(const int2*)(g_tmp + (size_t)s0 * HID + fg * 4);
        int2 v1 = *(const int2*)(g_tmp + (size_t)s1 * HID + fg * 4);
        float2 a0 = __half22float2(*(__half2*)&v0.x);
        float2 b0 = __half22float2(*(__half2*)&v0.y);
        float2 a1 = __half22float2(*(__half2*)&v1.x);
        float2 b1f = __half22float2(*(__half2*)&v1.y);
        ax += a0.x + a1.x; ay += a0.y + a1.y;
        az += b0.x + b1f.x; aw += b0.y + b1f.y;
    }
    if (e + 4 <= e1) {
        int s = g_csr_src[e + eidx];
        int2 v = *(const int2*)(g_tmp + (size_t)s * HID + fg * 4);
        float2 f0 = __half22float2(*(__half2*)&v.x);
        float2 f1 = __half22float2(*(__half2*)&v.y);
        ax += f0.x; ay += f0.y; az += f1.x; aw += f1.y;
        e += 4;
    }
    if (eidx < e1 - e) {
        int s = g_csr_src[e + eidx];
        int2 v = *(const int2*)(g_tmp + (size_t)s * HID + fg * 4);
        float2 f0 = __half22float2(*(__half2*)&v.x);
        float2 f1 = __half22float2(*(__half2*)&v.y);
        ax += f0.x; ay += f0.y; az += f1.x; aw += f1.y;
    }
#pragma unroll
    for (int o = 8; o <= 16; o <<= 1) {
        ax += __shfl_xor_sync(0xffffffffu, ax, o);
        ay += __shfl_xor_sync(0xffffffffu, ay, o);
        az += __shfl_xor_sync(0xffffffffu, az, o);
        aw += __shfl_xor_sync(0xffffffffu, aw, o);
    }
    // self loop
    {
        int2 v = *(const int2*)(g_tmp + (size_t)n * HID + fg * 4);
        float2 f0 = __half22float2(*(__half2*)&v.x);
        float2 f1 = __half22float2(*(__half2*)&v.y);
        ax += f0.x; ay += f0.y; az += f1.x; aw += f1.y;
    }
    float di = g_dinv[n];
    float4 bv = *(const float4*)(b1 + fg * 4);
    float4 y;
    y.x = fmaxf(fmaf(di, ax, bv.x), 0.0f);
    y.y = fmaxf(fmaf(di, ay, bv.y), 0.0f);
    y.z = fmaxf(fmaf(di, az, bv.z), 0.0f);
    y.w = fmaxf(fmaf(di, aw, bv.w), 0.0f);
    if (eidx == 0) *(float4*)&sy[w][fg * 4] = y;
    __syncwarp();
    float t = 0.0f;
#pragma unroll
    for (int k = 0; k < HID; k++) t = fmaf(sy[w][k], sW[k * HID + lane], t);
    g_acc[(size_t)n * HID + lane] = __float2half_rn(di * t);
}

// ---------------- fused: agg(L2) + relu + dot W3 + scale -> g_tmp3 ----------------
__global__ void k_agg_xf3(const float* __restrict__ W3, const float* __restrict__ b2) {
    int tid = threadIdx.x;
    int w = tid >> 5, lane = tid & 31;
    int n = blockIdx.x * 8 + w;
    if (n >= N_NODES) return;  // warp-uniform
    int eidx = lane >> 3, fg = lane & 7;
    int e = g_rowptr[n];
    int e1 = g_rowptr[n + 1];
    float ax = 0.f, ay = 0.f, az = 0.f, aw = 0.f;
    for (; e + 8 <= e1; e += 8) {
        int s0 = g_csr_src[e + eidx];
        int s1 = g_csr_src[e + 4 + eidx];
        int2 v0 = *(const int2*)(g_acc + (size_t)s0 * HID + fg * 4);
        int2 v1 = *(const int2*)(g_acc + (size_t)s1 * HID + fg * 4);
        float2 a0 = __half22float2(*(__half2*)&v0.x);
        float2 b0 = __half22float2(*(__half2*)&v0.y);
        float2 a1 = __half22float2(*(__half2*)&v1.x);
        float2 b1f = __half22float2(*(__half2*)&v1.y);
        ax += a0.x + a1.x; ay += a0.y + a1.y;
        az += b0.x + b1f.x; aw += b0.y + b1f.y;
    }
    if (e + 4 <= e1) {
        int s = g_csr_src[e + eidx];
        int2 v = *(const int2*)(g_acc + (size_t)s * HID + fg * 4);
        float2 f0 = __half22float2(*(__half2*)&v.x);
        float2 f1 = __half22float2(*(__half2*)&v.y);
        ax += f0.x; ay += f0.y; az += f1.x; aw += f1.y;
        e += 4;
    }
    if (eidx < e1 - e) {
        int s = g_csr_src[e + eidx];
        int2 v = *(const int2*)(g_acc + (size_t)s * HID + fg * 4);
        float2 f0 = __half22float2(*(__half2*)&v.x);
        float2 f1 = __half22float2(*(__half2*)&v.y);
        ax += f0.x; ay += f0.y; az += f1.x; aw += f1.y;
    }
#pragma unroll
    for (int o = 8; o <= 16; o <<= 1) {
        ax += __shfl_xor_sync(0xffffffffu, ax, o);
        ay += __shfl_xor_sync(0xffffffffu, ay, o);
        az += __shfl_xor_sync(0xffffffffu, az, o);
        aw += __shfl_xor_sync(0xffffffffu, aw, o);
    }
    {
        int2 v = *(const int2*)(g_acc + (size_t)n * HID + fg * 4);
        float2 f0 = __half22float2(*(__half2*)&v.x);
        float2 f1 = __half22float2(*(__half2*)&v.y);
        ax += f0.x; ay += f0.y; az += f1.x; aw += f1.y;
    }
    float di = g_dinv[n];
    float4 bv = *(const float4*)(b2 + fg * 4);
    float4 wv = *(const float4*)(W3 + fg * 4);
    float t = fmaxf(fmaf(di, ax, bv.x), 0.0f) * wv.x
            + fmaxf(fmaf(di, ay, bv.y), 0.0f) * wv.y
            + fmaxf(fmaf(di, az, bv.z), 0.0f) * wv.z
            + fmaxf(fmaf(di, aw, bv.w), 0.0f) * wv.w;
#pragma unroll
    for (int o = 1; o <= 4; o <<= 1) t += __shfl_xor_sync(0xffffffffu, t, o);
    if (lane == 0) g_tmp3[n] = di * t;
}

// ---------------- scalar gather + final sigmoid ----------------
__global__ void k_agg1_final(const float* __restrict__ b3, float* __restrict__ out) {
    int n = blockIdx.x * blockDim.x + threadIdx.x;
    if (n >= N_NODES) return;
    int e = g_rowptr[n];
    int e1 = g_rowptr[n + 1];
    float a = g_tmp3[n];  // self loop
    for (; e + 4 <= e1; e += 4) {
        float v0 = g_tmp3[g_csr_src[e + 0]];
        float v1 = g_tmp3[g_csr_src[e + 1]];
        float v2 = g_tmp3[g_csr_src[e + 2]];
        float v3 = g_tmp3[g_csr_src[e + 3]];
        a += (v0 + v1) + (v2 + v3);
    }
    for (; e < e1; e++) a += g_tmp3[g_csr_src[e]];
    float z = fmaf(g_dinv[n], a, b3[0]);
    out[n] = 1.0f / (1.0f + __expf(-z));
}

extern "C" void kernel_launch(void* const* d_in, const int* in_sizes, int n_in,
                              void* d_out, int out_size) {
    // Resolve inputs by element count — robust to metadata ordering.
    int ix = -1, ie = -1, iw1 = -1, iw2 = -1, ib3 = -1;
    int i32[3], n32 = 0;
    for (int i = 0; i < n_in; i++) {
        switch (in_sizes[i]) {
            case 19200000: ix = i; break;
            case 4800000:  ie = i; break;
            case 4096:     iw1 = i; break;
            case 1024:     iw2 = i; break;
            case 1:        ib3 = i; break;
            case 32:       if (n32 < 3) i32[n32++] = i; break;
            default: break;
        }
    }
    int ib1, ib2, iw3;
    if (ie == 1) {  // dict order: x, edge_index, W1, b1, W2, b2, W3, b3
        ib1 = i32[0]; ib2 = i32[1]; iw3 = i32[2];
    } else {        // alphabetical: W1, W2, W3, b1, b2, b3, edge_index, x
        iw3 = i32[0]; ib1 = i32[1]; ib2 = i32[2];
    }

    const float* x  = (const float*)d_in[ix];
    const int* ei   = (const int*)d_in[ie];   // [2, E] int32
    const float* W1 = (const float*)d_in[iw1];
    const float* b1 = (const float*)d_in[ib1];
    const float* W2 = (const float*)d_in[iw2];
    const float* b2 = (const float*)d_in[ib2];
    const float* W3 = (const float*)d_in[iw3];
    const float* b3 = (const float*)d_in[ib3];
    float* out = (float*)d_out;

    const int* src = ei;
    const int* dst = ei + N_EDGES;

    const int T = 256;
    int nblk_nodes = (N_NODES + T - 1) / T;
    int nblk_rows8 = (N_NODES + 7) / 8;

    // zero counters via memset node (graph-capturable)
    void* cnt_ptr = nullptr;
    cudaGetSymbolAddress(&cnt_ptr, g_cnt);
    cudaMemsetAsync(cnt_ptr, 0, N_NODES * sizeof(int), 0);

    // F1: hist (1/3 of blocks) + wmma xform1 raw (2/3)
    k_F1<<<3 * HIST_BLKS, T>>>(dst, x, W1);
    k_scan_a<<<SCAN_NB, SCAN_BS>>>();
    k_scan_c<<<SCAN_NB, SCAN_BS>>>();   // fused scan_b + scan_c
    // F2: fill (even) + dinv-scale of g_tmp (odd)
    k_F2<<<2 * EDGE_BLKS, T>>>(src, dst);

    k_agg_xf2<<<nblk_rows8, T>>>(W2, b1);    // agg L1 + relu + @W2
    k_agg_xf3<<<nblk_rows8, T>>>(W3, b2);    // agg L2 + relu + dot W3
    k_agg1_final<<<nblk_nodes, T>>>(b3, out);
}